// round 1
// baseline (speedup 1.0000x reference)
#include <cuda_runtime.h>
#include <cuda_bf16.h>

#define Bq    8
#define CIN   128
#define COUT  128
#define HH    256
#define WW    256
#define SDIM  512

#define TH    8          // output rows per block tile
#define TW    32         // output cols per block tile
#define OCB   16         // output channels per block tile
#define XT_H  (TH + 2)   // 10  (halo)
#define XT_W  (TW + 2)   // 34  (halo)
#define XT_N  (XT_H * XT_W)  // 340

// tiny scratch (allocation-free rule: __device__ globals)
__device__ float g_style[Bq * CIN];
__device__ float g_demod[Bq * COUT];

// ---------------------------------------------------------------------------
// Kernel 1: style = w @ style_W^T + style_b ;  demod = rsqrt(s2 @ S^T + eps)
// grid(8 blocks = batch), 128 threads (= channel)
// ---------------------------------------------------------------------------
__global__ void style_demod_kernel(const float* __restrict__ w,
                                   const float* __restrict__ style_W,
                                   const float* __restrict__ style_b,
                                   const float* __restrict__ weight) {
    const int b = blockIdx.x;
    const int o = threadIdx.x;           // 0..127 (channel index)
    __shared__ float s2[CIN];

    // style[b,o] = sum_k w[b,k] * style_W[o,k] + style_b[o]
    const float4* wv = (const float4*)(w + (size_t)b * SDIM);
    const float4* Wv = (const float4*)(style_W + (size_t)o * SDIM);
    float acc = 0.f;
    #pragma unroll 4
    for (int k = 0; k < SDIM / 4; k++) {
        float4 a = wv[k];
        float4 c = Wv[k];
        acc += a.x * c.x + a.y * c.y + a.z * c.z + a.w * c.w;
    }
    float st = acc + style_b[o];
    g_style[b * CIN + o] = st;
    s2[o] = st * st;
    __syncthreads();

    // demod[b,o] = rsqrt( sum_i s2[i] * sum_t weight[o,i,t]^2 + 1e-8 )
    float sum = 0.f;
    const float* wo = weight + (size_t)o * CIN * 9;
    #pragma unroll 1
    for (int i = 0; i < CIN; i++) {
        float ss = 0.f;
        #pragma unroll
        for (int t = 0; t < 9; t++) {
            float v = wo[i * 9 + t];
            ss += v * v;
        }
        sum += s2[i] * ss;
    }
    g_demod[b * COUT + o] = rsqrtf(sum + 1e-8f);
}

// ---------------------------------------------------------------------------
// Kernel 2: direct 3x3 SAME conv, per-sample:
//   out[b,o,y,x] = d[b,o] * sum_{i,ky,kx} weight[o,i,ky,kx]*(style[b,i]*x[b,i,y+ky-1,x+kx-1]) + bias[o]
// Block tile: 16 oc x 8 h x 32 w. Thread: 2 oc x 8 rows x 1 col.
// Software-pipelined x/w loads; lane==column smem reads (conflict-free).
// ---------------------------------------------------------------------------
__global__ __launch_bounds__(256, 2)
void conv_kernel(const float* __restrict__ x,
                 const float* __restrict__ weight,
                 const float* __restrict__ bias,
                 float* __restrict__ out) {
    __shared__ float xs[XT_N];       // style-scaled x halo tile
    __shared__ float ws[OCB * 9];    // weights for this oc tile, current cin
    __shared__ float sstyle[CIN];    // per-batch styles

    const int tid = threadIdx.x;
    const int b   = blockIdx.z;
    const int og  = blockIdx.y;                 // oc tile index (0..7)
    const int sp  = blockIdx.x;                 // spatial tile (0..255)
    const int xt  = sp & 7;                     // 8 tiles across W
    const int yt  = sp >> 3;                    // 32 tiles across H
    const int x0  = xt * TW;
    const int y0  = yt * TH;

    const int tx  = tid & 31;                   // column within tile
    const int ocg = tid >> 5;                   // 0..7 -> oc pair
    const int oc0 = og * OCB + ocg * 2;

    if (tid < CIN) sstyle[tid] = g_style[b * CIN + tid];

    // ---- x loader mapping: elements e0 = tid, e1 = tid + 256 (if < 340)
    const int e0 = tid, e1 = tid + 256;
    const int r0 = e0 / XT_W, c0 = e0 - r0 * XT_W;
    const int r1 = e1 / XT_W, c1 = e1 - r1 * XT_W;
    const int gy0 = y0 - 1 + r0, gx0 = x0 - 1 + c0;
    const int gy1 = y0 - 1 + r1, gx1 = x0 - 1 + c1;
    const bool p0 = (gy0 >= 0) && (gy0 < HH) && (gx0 >= 0) && (gx0 < WW);
    const bool p1 = (e1 < XT_N) && (gy1 >= 0) && (gy1 < HH) && (gx1 >= 0) && (gx1 < WW);
    const float* xb = x + (size_t)b * CIN * HH * WW;
    const long off0 = (long)gy0 * WW + gx0;
    const long off1 = (long)gy1 * WW + gx1;

    // ---- weight loader mapping: tid < 144 loads weight[og*16 + tid/9][ci][tid%9]
    const bool pw  = tid < OCB * 9;
    const int oc_l = tid / 9;
    const int t_l  = tid - oc_l * 9;
    const float* wbase = weight + ((size_t)(og * OCB + oc_l)) * CIN * 9 + t_l;

    float acc[2][TH];
    #pragma unroll
    for (int o = 0; o < 2; o++)
        #pragma unroll
        for (int r = 0; r < TH; r++) acc[o][r] = 0.f;

    // prologue: prefetch ci = 0
    float xr0 = p0 ? __ldg(xb + off0) : 0.f;
    float xr1 = p1 ? __ldg(xb + off1) : 0.f;
    float wr  = pw ? __ldg(wbase) : 0.f;

    __syncthreads();  // sstyle ready

    #pragma unroll 1
    for (int ci = 0; ci < CIN; ci++) {
        const float sv = sstyle[ci];
        xs[e0] = xr0 * sv;
        if (e1 < XT_N) xs[e1] = xr1 * sv;
        if (pw) ws[tid] = wr;
        __syncthreads();

        // prefetch next cin while computing from smem
        if (ci + 1 < CIN) {
            const float* xc = xb + (size_t)(ci + 1) * HH * WW;
            xr0 = p0 ? __ldg(xc + off0) : 0.f;
            xr1 = p1 ? __ldg(xc + off1) : 0.f;
            wr  = pw ? __ldg(wbase + (size_t)(ci + 1) * 9) : 0.f;
        }

        // load 10x3 x-window into regs (lane = column -> conflict-free LDS)
        float xw[XT_H][3];
        #pragma unroll
        for (int r = 0; r < XT_H; r++)
            #pragma unroll
            for (int c = 0; c < 3; c++)
                xw[r][c] = xs[r * XT_W + tx + c];

        // 2 oc x 9 taps x 8 rows = 144 FFMA
        #pragma unroll
        for (int o = 0; o < 2; o++) {
            #pragma unroll
            for (int ky = 0; ky < 3; ky++) {
                #pragma unroll
                for (int kx = 0; kx < 3; kx++) {
                    const float wv = ws[(ocg * 2 + o) * 9 + ky * 3 + kx];
                    #pragma unroll
                    for (int r = 0; r < TH; r++)
                        acc[o][r] += wv * xw[r + ky][kx];
                }
            }
        }
        __syncthreads();
    }

    // epilogue: demod + bias, coalesced stores
    const float d0 = g_demod[b * COUT + oc0];
    const float d1 = g_demod[b * COUT + oc0 + 1];
    const float b0 = bias[oc0];
    const float b1 = bias[oc0 + 1];
    float* outb = out + (((size_t)b * COUT + oc0) * HH) * WW;
    #pragma unroll
    for (int r = 0; r < TH; r++) {
        outb[(size_t)(y0 + r) * WW + x0 + tx]                          = acc[0][r] * d0 + b0;
        outb[(size_t)HH * WW + (size_t)(y0 + r) * WW + x0 + tx]        = acc[1][r] * d1 + b1;
    }
}

// ---------------------------------------------------------------------------
extern "C" void kernel_launch(void* const* d_in, const int* in_sizes, int n_in,
                              void* d_out, int out_size) {
    const float* x       = (const float*)d_in[0];  // [8,128,256,256]
    const float* w       = (const float*)d_in[1];  // [8,512]
    const float* weight  = (const float*)d_in[2];  // [128,128,3,3]
    const float* style_W = (const float*)d_in[3];  // [128,512]
    const float* style_b = (const float*)d_in[4];  // [128]
    const float* bias    = (const float*)d_in[5];  // [128]
    float* out = (float*)d_out;                    // [8,128,256,256]

    style_demod_kernel<<<Bq, 128>>>(w, style_W, style_b, weight);

    dim3 grid(256 /*spatial tiles*/, COUT / OCB /*=8*/, Bq /*=8*/);
    conv_kernel<<<grid, 256>>>(x, weight, bias, out);
}

// round 2
// speedup vs baseline: 1.0002x; 1.0002x over previous
#include <cuda_runtime.h>
#include <cuda_bf16.h>

#define Bq    8
#define CIN   128
#define COUT  128
#define HH    256
#define WW    256
#define SDIM  512

#define TH    8          // output rows per block tile
#define TW    32         // output cols per block tile
#define OCB   16         // output channels per block tile
#define XT_H  (TH + 2)   // 10  (halo)
#define XT_W  (TW + 2)   // 34  (halo)
#define XT_N  (XT_H * XT_W)  // 340

// tiny scratch (allocation-free rule: __device__ globals)
__device__ float g_style[Bq * CIN];
__device__ float g_demod[Bq * COUT];

// ---------------------------------------------------------------------------
// Kernel 1: style = w @ style_W^T + style_b ;  demod = rsqrt(s2 @ S^T + eps)
// grid(8 blocks = batch), 128 threads (= channel)
// ---------------------------------------------------------------------------
__global__ void style_demod_kernel(const float* __restrict__ w,
                                   const float* __restrict__ style_W,
                                   const float* __restrict__ style_b,
                                   const float* __restrict__ weight) {
    const int b = blockIdx.x;
    const int o = threadIdx.x;           // 0..127 (channel index)
    __shared__ float s2[CIN];

    // style[b,o] = sum_k w[b,k] * style_W[o,k] + style_b[o]
    const float4* wv = (const float4*)(w + (size_t)b * SDIM);
    const float4* Wv = (const float4*)(style_W + (size_t)o * SDIM);
    float acc = 0.f;
    #pragma unroll 4
    for (int k = 0; k < SDIM / 4; k++) {
        float4 a = wv[k];
        float4 c = Wv[k];
        acc += a.x * c.x + a.y * c.y + a.z * c.z + a.w * c.w;
    }
    float st = acc + style_b[o];
    g_style[b * CIN + o] = st;
    s2[o] = st * st;
    __syncthreads();

    // demod[b,o] = rsqrt( sum_i s2[i] * sum_t weight[o,i,t]^2 + 1e-8 )
    float sum = 0.f;
    const float* wo = weight + (size_t)o * CIN * 9;
    #pragma unroll 1
    for (int i = 0; i < CIN; i++) {
        float ss = 0.f;
        #pragma unroll
        for (int t = 0; t < 9; t++) {
            float v = wo[i * 9 + t];
            ss += v * v;
        }
        sum += s2[i] * ss;
    }
    g_demod[b * COUT + o] = rsqrtf(sum + 1e-8f);
}

// ---------------------------------------------------------------------------
// Kernel 2: direct 3x3 SAME conv, per-sample:
//   out[b,o,y,x] = d[b,o] * sum_{i,ky,kx} weight[o,i,ky,kx]*(style[b,i]*x[b,i,y+ky-1,x+kx-1]) + bias[o]
// Block tile: 16 oc x 8 h x 32 w. Thread: 2 oc x 8 rows x 1 col.
// Software-pipelined x/w loads; lane==column smem reads (conflict-free).
// ---------------------------------------------------------------------------
__global__ __launch_bounds__(256, 2)
void conv_kernel(const float* __restrict__ x,
                 const float* __restrict__ weight,
                 const float* __restrict__ bias,
                 float* __restrict__ out) {
    __shared__ float xs[XT_N];       // style-scaled x halo tile
    __shared__ float ws[OCB * 9];    // weights for this oc tile, current cin
    __shared__ float sstyle[CIN];    // per-batch styles

    const int tid = threadIdx.x;
    const int b   = blockIdx.z;
    const int og  = blockIdx.y;                 // oc tile index (0..7)
    const int sp  = blockIdx.x;                 // spatial tile (0..255)
    const int xt  = sp & 7;                     // 8 tiles across W
    const int yt  = sp >> 3;                    // 32 tiles across H
    const int x0  = xt * TW;
    const int y0  = yt * TH;

    const int tx  = tid & 31;                   // column within tile
    const int ocg = tid >> 5;                   // 0..7 -> oc pair
    const int oc0 = og * OCB + ocg * 2;

    if (tid < CIN) sstyle[tid] = g_style[b * CIN + tid];

    // ---- x loader mapping: elements e0 = tid, e1 = tid + 256 (if < 340)
    const int e0 = tid, e1 = tid + 256;
    const int r0 = e0 / XT_W, c0 = e0 - r0 * XT_W;
    const int r1 = e1 / XT_W, c1 = e1 - r1 * XT_W;
    const int gy0 = y0 - 1 + r0, gx0 = x0 - 1 + c0;
    const int gy1 = y0 - 1 + r1, gx1 = x0 - 1 + c1;
    const bool p0 = (gy0 >= 0) && (gy0 < HH) && (gx0 >= 0) && (gx0 < WW);
    const bool p1 = (e1 < XT_N) && (gy1 >= 0) && (gy1 < HH) && (gx1 >= 0) && (gx1 < WW);
    const float* xb = x + (size_t)b * CIN * HH * WW;
    const long off0 = (long)gy0 * WW + gx0;
    const long off1 = (long)gy1 * WW + gx1;

    // ---- weight loader mapping: tid < 144 loads weight[og*16 + tid/9][ci][tid%9]
    const bool pw  = tid < OCB * 9;
    const int oc_l = tid / 9;
    const int t_l  = tid - oc_l * 9;
    const float* wbase = weight + ((size_t)(og * OCB + oc_l)) * CIN * 9 + t_l;

    float acc[2][TH];
    #pragma unroll
    for (int o = 0; o < 2; o++)
        #pragma unroll
        for (int r = 0; r < TH; r++) acc[o][r] = 0.f;

    // prologue: prefetch ci = 0
    float xr0 = p0 ? __ldg(xb + off0) : 0.f;
    float xr1 = p1 ? __ldg(xb + off1) : 0.f;
    float wr  = pw ? __ldg(wbase) : 0.f;

    __syncthreads();  // sstyle ready

    #pragma unroll 1
    for (int ci = 0; ci < CIN; ci++) {
        const float sv = sstyle[ci];
        xs[e0] = xr0 * sv;
        if (e1 < XT_N) xs[e1] = xr1 * sv;
        if (pw) ws[tid] = wr;
        __syncthreads();

        // prefetch next cin while computing from smem
        if (ci + 1 < CIN) {
            const float* xc = xb + (size_t)(ci + 1) * HH * WW;
            xr0 = p0 ? __ldg(xc + off0) : 0.f;
            xr1 = p1 ? __ldg(xc + off1) : 0.f;
            wr  = pw ? __ldg(wbase + (size_t)(ci + 1) * 9) : 0.f;
        }

        // load 10x3 x-window into regs (lane = column -> conflict-free LDS)
        float xw[XT_H][3];
        #pragma unroll
        for (int r = 0; r < XT_H; r++)
            #pragma unroll
            for (int c = 0; c < 3; c++)
                xw[r][c] = xs[r * XT_W + tx + c];

        // 2 oc x 9 taps x 8 rows = 144 FFMA
        #pragma unroll
        for (int o = 0; o < 2; o++) {
            #pragma unroll
            for (int ky = 0; ky < 3; ky++) {
                #pragma unroll
                for (int kx = 0; kx < 3; kx++) {
                    const float wv = ws[(ocg * 2 + o) * 9 + ky * 3 + kx];
                    #pragma unroll
                    for (int r = 0; r < TH; r++)
                        acc[o][r] += wv * xw[r + ky][kx];
                }
            }
        }
        __syncthreads();
    }

    // epilogue: demod + bias, coalesced stores
    const float d0 = g_demod[b * COUT + oc0];
    const float d1 = g_demod[b * COUT + oc0 + 1];
    const float b0 = bias[oc0];
    const float b1 = bias[oc0 + 1];
    float* outb = out + (((size_t)b * COUT + oc0) * HH) * WW;
    #pragma unroll
    for (int r = 0; r < TH; r++) {
        outb[(size_t)(y0 + r) * WW + x0 + tx]                          = acc[0][r] * d0 + b0;
        outb[(size_t)HH * WW + (size_t)(y0 + r) * WW + x0 + tx]        = acc[1][r] * d1 + b1;
    }
}

// ---------------------------------------------------------------------------
extern "C" void kernel_launch(void* const* d_in, const int* in_sizes, int n_in,
                              void* d_out, int out_size) {
    const float* x       = (const float*)d_in[0];  // [8,128,256,256]
    const float* w       = (const float*)d_in[1];  // [8,512]
    const float* weight  = (const float*)d_in[2];  // [128,128,3,3]
    const float* style_W = (const float*)d_in[3];  // [128,512]
    const float* style_b = (const float*)d_in[4];  // [128]
    const float* bias    = (const float*)d_in[5];  // [128]
    float* out = (float*)d_out;                    // [8,128,256,256]

    style_demod_kernel<<<Bq, 128>>>(w, style_W, style_b, weight);

    dim3 grid(256 /*spatial tiles*/, COUT / OCB /*=8*/, Bq /*=8*/);
    conv_kernel<<<grid, 256>>>(x, weight, bias, out);
}

// round 4
// speedup vs baseline: 2.1071x; 2.1067x over previous
#include <cuda_runtime.h>
#include <cstdint>

#define Bq    8
#define CIN   128
#define COUT  128
#define HH    256
#define WW    256
#define SDIM  512

#define STG_W 264                      // stage stride (floats), 264 % 32 == 8 -> conflict-free
#define OFF_STYLE 0
#define OFF_STAGE 512
#define OFF_A     (512 + 32*STG_W*4)   // 34304
#define A_SUB     16384                // 4kk x 8mt x 32T x 16B
#define OFF_B     (OFF_A + 2*A_SUB)    // 67072
#define B_SUB     32768                // 4kk x 32nt x 32T x 8B
#define SMEM_TOTAL (OFF_B + 2*B_SUB)   // 132608

__device__ float g_style[Bq * CIN];
__device__ float g_demod[Bq * COUT];
__device__ float g_wA[36 * 4096];      // 36 sub-chunks x (4kk x 8mt x 32T x 4) fragment-ordered tf32

__device__ __forceinline__ float tf32r(float f) {
    uint32_t u;
    asm("cvt.rn.tf32.f32 %0, %1;" : "=r"(u) : "f"(f));
    return __uint_as_float(u);
}

#define MMA_TF32(d, a, bb)                                               \
    asm volatile("mma.sync.aligned.m16n8k8.row.col.f32.tf32.tf32.f32 "   \
                 "{%0,%1,%2,%3}, {%4,%5,%6,%7}, {%8,%9}, {%0,%1,%2,%3};" \
                 : "+f"((d)[0]), "+f"((d)[1]), "+f"((d)[2]), "+f"((d)[3])\
                 : "r"((a)[0]), "r"((a)[1]), "r"((a)[2]), "r"((a)[3]),   \
                   "r"((bb)[0]), "r"((bb)[1]))

// ---------------------------------------------------------------------------
// style + demod (proven, rel_err 7e-7 path)
// ---------------------------------------------------------------------------
__global__ void style_demod_kernel(const float* __restrict__ w,
                                   const float* __restrict__ style_W,
                                   const float* __restrict__ style_b,
                                   const float* __restrict__ weight) {
    const int b = blockIdx.x, o = threadIdx.x;
    __shared__ float s2[CIN];
    const float4* wv = (const float4*)(w + (size_t)b * SDIM);
    const float4* Wv = (const float4*)(style_W + (size_t)o * SDIM);
    float acc = 0.f;
    #pragma unroll 4
    for (int k = 0; k < SDIM / 4; k++) {
        float4 a = wv[k], c = Wv[k];
        acc += a.x * c.x + a.y * c.y + a.z * c.z + a.w * c.w;
    }
    float st = acc + style_b[o];
    g_style[b * CIN + o] = st;
    s2[o] = st * st;
    __syncthreads();
    float sum = 0.f;
    const float* wo = weight + (size_t)o * CIN * 9;
    #pragma unroll 1
    for (int i = 0; i < CIN; i++) {
        float ss = 0.f;
        #pragma unroll
        for (int t = 0; t < 9; t++) { float v = wo[i * 9 + t]; ss += v * v; }
        sum += s2[i] * ss;
    }
    g_demod[b * COUT + o] = rsqrtf(sum + 1e-8f);
}

// ---------------------------------------------------------------------------
// prepack weights into mma.sync A-fragment order, tf32-rounded.
// idx = ((G*4 + kk)*8 + mt)*32*4 + T*4 + j ; G = (dy*4+chunk)*3 + dx
// A element (m16n8k8 row-major): a_j at row = mt*16 + (T>>2) + 8*(j&1),
//                                 k_loc = kk*8 + (T&3) + 4*(j>>1)
// ---------------------------------------------------------------------------
__global__ void prepack_kernel(const float* __restrict__ weight) {
    int idx = blockIdx.x * 256 + threadIdx.x;      // < 147456
    int j  = idx & 3;
    int T  = (idx >> 2) & 31;
    int mt = (idx >> 7) & 7;
    int kk = (idx >> 10) & 3;
    int G  = idx >> 12;                            // 0..35
    int dx = G % 3;
    int g  = G / 3;
    int dy = g >> 2, chunk = g & 3;
    int m  = mt * 16 + (T >> 2) + 8 * (j & 1);
    int cl = kk * 8 + (T & 3) + 4 * (j >> 1);
    int c  = chunk * 32 + cl;
    float v = weight[((size_t)m * CIN + c) * 9 + dy * 3 + dx];
    g_wA[idx] = tf32r(v);
}

// ---------------------------------------------------------------------------
// main conv: CTA = (y, b). M=128 x N=256 x K=1152 tf32 mma.sync GEMM.
// ---------------------------------------------------------------------------
__global__ __launch_bounds__(512, 1)
void conv_mma_kernel(const float* __restrict__ x,
                     const float* __restrict__ bias,
                     float* __restrict__ out) {
    extern __shared__ char smem[];
    float* styl  = (float*)(smem + OFF_STYLE);
    float* stage = (float*)(smem + OFF_STAGE);

    const int tid  = threadIdx.x;
    const int lane = tid & 31;
    const int warp = tid >> 5;
    const int wm   = warp >> 2;     // 0..3  (M)
    const int wn   = warp & 3;      // 0..3  (N)
    const int y    = blockIdx.x;
    const int b    = blockIdx.y;

    if (tid < CIN) styl[tid] = g_style[b * CIN + tid];

    float acc[2][8][4];
    #pragma unroll
    for (int m = 0; m < 2; m++)
        #pragma unroll
        for (int n = 0; n < 8; n++)
            #pragma unroll
            for (int j = 0; j < 4; j++) acc[m][n][j] = 0.f;

    auto compute = [&](int sb) {
        const float4* Af = (const float4*)(smem + OFF_A + sb * A_SUB);
        const float2* Bf = (const float2*)(smem + OFF_B + sb * B_SUB);
        #pragma unroll
        for (int kk = 0; kk < 4; kk++) {
            uint32_t a[2][4];
            #pragma unroll
            for (int m = 0; m < 2; m++) {
                float4 av = Af[(kk * 8 + wm * 2 + m) * 32 + lane];
                a[m][0] = __float_as_uint(av.x);
                a[m][1] = __float_as_uint(av.y);
                a[m][2] = __float_as_uint(av.z);
                a[m][3] = __float_as_uint(av.w);
            }
            uint32_t bb[8][2];
            #pragma unroll
            for (int n = 0; n < 8; n++) {
                float2 bv = Bf[(kk * 32 + wn * 8 + n) * 32 + lane];
                bb[n][0] = __float_as_uint(bv.x);
                bb[n][1] = __float_as_uint(bv.y);
            }
            #pragma unroll
            for (int m = 0; m < 2; m++)
                #pragma unroll
                for (int n = 0; n < 8; n++)
                    MMA_TF32(acc[m][n], a[m], bb[n]);
        }
    };

    __syncthreads();   // styl visible

    int s = 0;
    #pragma unroll 1
    for (int g = 0; g < 12; g++) {
        const int dy = g >> 2, chunk = g & 3;
        const int yr = y + dy - 1;
        const bool yok = (yr >= 0) && (yr < HH);
        const int c0 = chunk * 32;

        // fill stage: 32 ch x 258 halo px, style-scaled, tf32-rounded
        #pragma unroll 1
        for (int it = tid; it < 32 * 258; it += 512) {
            int c = it / 258;
            int q = it - c * 258;
            int gx = q - 1;
            float v = 0.f;
            if (yok && (unsigned)gx < (unsigned)WW)
                v = x[(((size_t)b * CIN + c0 + c) * HH + yr) * WW + gx] * styl[c0 + c];
            stage[c * STG_W + q] = tf32r(v);
        }
        __syncthreads();

        #pragma unroll 1
        for (int dx = 0; dx < 3; dx++, s++) {
            // build A (verbatim fragment copy from prepacked gmem)
            {
                float4* dst = (float4*)(smem + OFF_A + (s & 1) * A_SUB);
                const float4* src = (const float4*)(g_wA + (size_t)s * 4096);
                dst[tid]       = src[tid];
                dst[tid + 512] = src[tid + 512];
            }
            // build B in fragment order: warp writes 8 (kk,nt) blocks, 256B each
            {
                float2* Bf = (float2*)(smem + OFF_B + (s & 1) * B_SUB);
                const int t  = lane & 3;
                const int gg = lane >> 2;
                #pragma unroll
                for (int i = 0; i < 8; i++) {
                    int pi = warp * 8 + i;          // 0..127
                    int kk = pi >> 5, nt = pi & 31;
                    int q  = nt * 8 + gg + dx;
                    float v0 = stage[(kk * 8 + t)     * STG_W + q];
                    float v1 = stage[(kk * 8 + t + 4) * STG_W + q];
                    Bf[pi * 32 + lane] = make_float2(v0, v1);
                }
            }
            if (s > 0) compute((s - 1) & 1);
            __syncthreads();
        }
    }
    compute(1);   // s = 35

    // epilogue: demod + bias, float2 stores (4 threads per 32B sector)
    #pragma unroll
    for (int m = 0; m < 2; m++) {
        const int oc0 = wm * 32 + m * 16 + (lane >> 2);
        const int oc1 = oc0 + 8;
        const float d0 = g_demod[b * COUT + oc0], bb0 = bias[oc0];
        const float d1 = g_demod[b * COUT + oc1], bb1 = bias[oc1];
        float* r0 = out + (((size_t)b * COUT + oc0) * HH + y) * WW;
        float* r1 = out + (((size_t)b * COUT + oc1) * HH + y) * WW;
        #pragma unroll
        for (int n = 0; n < 8; n++) {
            const int px = wn * 64 + n * 8 + (lane & 3) * 2;
            float2 v0 = make_float2(acc[m][n][0] * d0 + bb0, acc[m][n][1] * d0 + bb0);
            float2 v1 = make_float2(acc[m][n][2] * d1 + bb1, acc[m][n][3] * d1 + bb1);
            *(float2*)(r0 + px) = v0;
            *(float2*)(r1 + px) = v1;
        }
    }
}

// ---------------------------------------------------------------------------
extern "C" void kernel_launch(void* const* d_in, const int* in_sizes, int n_in,
                              void* d_out, int out_size) {
    const float* x       = (const float*)d_in[0];
    const float* w       = (const float*)d_in[1];
    const float* weight  = (const float*)d_in[2];
    const float* style_W = (const float*)d_in[3];
    const float* style_b = (const float*)d_in[4];
    const float* bias    = (const float*)d_in[5];
    float* out = (float*)d_out;

    cudaFuncSetAttribute(conv_mma_kernel,
                         cudaFuncAttributeMaxDynamicSharedMemorySize, SMEM_TOTAL);

    style_demod_kernel<<<Bq, 128>>>(w, style_W, style_b, weight);
    prepack_kernel<<<576, 256>>>(weight);
    dim3 grid(HH, Bq);
    conv_mma_kernel<<<grid, 512, SMEM_TOTAL>>>(x, bias, out);
}

// round 5
// speedup vs baseline: 2.9769x; 1.4128x over previous
#include <cuda_runtime.h>
#include <cstdint>

#define Bq    8
#define CIN   128
#define COUT  128
#define HH    256
#define WW    256
#define SDIM  512

#define STW   136          // stage stride (floats); 136 % 32 == 8 -> conflict-free B reads

__device__ float g_style[Bq * CIN];
__device__ float g_demod[Bq * COUT];
__device__ float g_W2[COUT * CIN];     // per-(o,i) tap-sum of squares
__device__ float g_wA[36 * 4096];      // fragment-ordered tf32 weights

__device__ __forceinline__ float tf32r(float f) {
    uint32_t u;
    asm("cvt.rn.tf32.f32 %0, %1;" : "=r"(u) : "f"(f));
    return __uint_as_float(u);
}

#define MMA_TF32(d, a, bb)                                               \
    asm volatile("mma.sync.aligned.m16n8k8.row.col.f32.tf32.tf32.f32 "   \
                 "{%0,%1,%2,%3}, {%4,%5,%6,%7}, {%8,%9}, {%0,%1,%2,%3};" \
                 : "+f"((d)[0]), "+f"((d)[1]), "+f"((d)[2]), "+f"((d)[3])\
                 : "r"((a)[0]), "r"((a)[1]), "r"((a)[2]), "r"((a)[3]),   \
                   "r"((bb)[0]), "r"((bb)[1]))

// ---------------------------------------------------------------------------
// prologue kernels (parallelized; old fused version cost 100 us)
// ---------------------------------------------------------------------------
__global__ void prep_style(const float* __restrict__ w,
                           const float* __restrict__ style_W,
                           const float* __restrict__ style_b) {
    const int b = blockIdx.x, o = threadIdx.x;
    const float4* wv = (const float4*)(w + (size_t)b * SDIM);
    const float4* Wv = (const float4*)(style_W + (size_t)o * SDIM);
    float acc = 0.f;
    #pragma unroll 8
    for (int k = 0; k < SDIM / 4; k++) {
        float4 a = wv[k], c = Wv[k];
        acc += a.x * c.x + a.y * c.y + a.z * c.z + a.w * c.w;
    }
    g_style[b * CIN + o] = acc + style_b[o];
}

__global__ void prep_w2(const float* __restrict__ weight) {
    int idx = blockIdx.x * 256 + threadIdx.x;       // < 16384
    const float* p = weight + (size_t)idx * 9;
    float s = 0.f;
    #pragma unroll
    for (int t = 0; t < 9; t++) { float v = p[t]; s += v * v; }
    g_W2[idx] = s;
}

__global__ void prep_demod(void) {
    int gw   = blockIdx.x * 8 + (threadIdx.x >> 5);  // 0..1023
    int lane = threadIdx.x & 31;
    int b = gw >> 7, o = gw & 127;
    float sum = 0.f;
    #pragma unroll
    for (int j = 0; j < 4; j++) {
        int i = lane + j * 32;
        float s = g_style[b * CIN + i];
        sum += s * s * g_W2[o * CIN + i];
    }
    #pragma unroll
    for (int d = 16; d > 0; d >>= 1)
        sum += __shfl_xor_sync(0xffffffffu, sum, d);
    if (lane == 0) g_demod[b * COUT + o] = rsqrtf(sum + 1e-8f);
}

// prepack weights into mma.sync A-fragment order (same mapping that passed R4)
__global__ void prepack_kernel(const float* __restrict__ weight) {
    int idx = blockIdx.x * 256 + threadIdx.x;      // < 147456
    int j  = idx & 3;
    int T  = (idx >> 2) & 31;
    int mt = (idx >> 7) & 7;
    int kk = (idx >> 10) & 3;
    int G  = idx >> 12;                            // 0..35
    int dx = G % 3;
    int g  = G / 3;
    int dy = g >> 2, chunk = g & 3;
    int m  = mt * 16 + (T >> 2) + 8 * (j & 1);
    int cl = kk * 8 + (T & 3) + 4 * (j >> 1);
    int c  = chunk * 32 + cl;
    g_wA[idx] = tf32r(weight[((size_t)m * CIN + c) * 9 + dy * 3 + dx]);
}

// ---------------------------------------------------------------------------
// main conv: CTA = (xhalf, y, b). M=128 x N=128 x K=1152.
// 8 warps: wm = warp>>1 (32 oc), wn = warp&1 (64 px). 2 CTAs/SM.
// B fragments read DIRECTLY from padded stage; A fragments LDG from L2/L1.
// ---------------------------------------------------------------------------
__global__ __launch_bounds__(256, 2)
void conv_mma_kernel(const float* __restrict__ x,
                     const float* __restrict__ bias,
                     float* __restrict__ out) {
    __shared__ float styl[CIN];
    __shared__ float stage[2][32 * STW];

    const int tid  = threadIdx.x;
    const int lane = tid & 31;
    const int warp = tid >> 5;
    const int wm   = warp >> 1;      // 0..3
    const int wn   = warp & 1;       // 0..1
    const int xh   = blockIdx.x;
    const int y    = blockIdx.y;
    const int b    = blockIdx.z;
    const int x0   = xh * 128;

    if (tid < CIN) styl[tid] = g_style[b * CIN + tid];
    __syncthreads();

    float acc[2][8][4];
    #pragma unroll
    for (int m = 0; m < 2; m++)
        #pragma unroll
        for (int n = 0; n < 8; n++)
            #pragma unroll
            for (int j = 0; j < 4; j++) acc[m][n][j] = 0.f;

    const int t  = lane & 3;
    const int gg = lane >> 2;

    // ---- fill one stage buffer for group g (32 ch x 130 halo px) ----
    auto fill = [&](int g, float* buf) {
        const int dy = g >> 2, chunk = g & 3;
        const int yr = y + dy - 1;
        const bool yok = (yr >= 0) && (yr < HH);
        const int c0 = chunk * 32;
        const float* xrow = x + (((size_t)b * CIN + c0) * HH + yr) * WW;
        #pragma unroll 1
        for (int it = tid; it < 32 * 130; it += 256) {
            int c = it / 130;
            int q = it - c * 130;
            int gx = x0 - 1 + q;
            float v = 0.f;
            if (yok && (unsigned)gx < (unsigned)WW)
                v = __ldg(xrow + (size_t)c * HH * WW + gx) * styl[c0 + c];
            buf[c * STW + q] = tf32r(v);
        }
    };

    // ---- one K-step: 64 MMAs, A rolling-prefetch from gmem, B from stage ----
    auto compute = [&](const float* stg, int dx, int s) {
        const float4* As = (const float4*)(g_wA + (size_t)s * 4096);
        float4 a0 = __ldg(As + ((wm * 2 + 0) * 32) + lane);
        float4 a1 = __ldg(As + ((wm * 2 + 1) * 32) + lane);
        #pragma unroll
        for (int kk = 0; kk < 4; kk++) {
            float4 n0, n1;
            if (kk < 3) {
                n0 = __ldg(As + (((kk + 1) * 8 + wm * 2 + 0) * 32) + lane);
                n1 = __ldg(As + (((kk + 1) * 8 + wm * 2 + 1) * 32) + lane);
            }
            const float* r0 = stg + (kk * 8 + t) * STW + gg + dx;
            const float* r1 = r0 + 4 * STW;
            uint32_t bb[8][2];
            #pragma unroll
            for (int n = 0; n < 8; n++) {
                int q = (wn * 8 + n) * 8;
                bb[n][0] = __float_as_uint(r0[q]);
                bb[n][1] = __float_as_uint(r1[q]);
            }
            uint32_t a[2][4] = {
                { __float_as_uint(a0.x), __float_as_uint(a0.y),
                  __float_as_uint(a0.z), __float_as_uint(a0.w) },
                { __float_as_uint(a1.x), __float_as_uint(a1.y),
                  __float_as_uint(a1.z), __float_as_uint(a1.w) } };
            #pragma unroll
            for (int m = 0; m < 2; m++)
                #pragma unroll
                for (int n = 0; n < 8; n++)
                    MMA_TF32(acc[m][n], a[m], bb[n]);
            if (kk < 3) { a0 = n0; a1 = n1; }
        }
    };

    fill(0, stage[0]);
    __syncthreads();

    #pragma unroll 1
    for (int g = 0; g < 12; g++) {
        const int cur = g & 1;
        const int s0  = g * 3;
        compute(stage[cur], 0, s0);
        if (g < 11) fill(g + 1, stage[cur ^ 1]);   // overlaps with dx=1,2 compute below
        compute(stage[cur], 1, s0 + 1);
        compute(stage[cur], 2, s0 + 2);
        __syncthreads();
    }

    // ---- epilogue: demod + bias, float2 stores ----
    #pragma unroll
    for (int m = 0; m < 2; m++) {
        const int oc0 = wm * 32 + m * 16 + (lane >> 2);
        const int oc1 = oc0 + 8;
        const float d0 = g_demod[b * COUT + oc0], bb0 = bias[oc0];
        const float d1 = g_demod[b * COUT + oc1], bb1 = bias[oc1];
        float* r0 = out + (((size_t)b * COUT + oc0) * HH + y) * WW;
        float* r1 = out + (((size_t)b * COUT + oc1) * HH + y) * WW;
        #pragma unroll
        for (int n = 0; n < 8; n++) {
            const int px = x0 + wn * 64 + n * 8 + (lane & 3) * 2;
            float2 v0 = make_float2(acc[m][n][0] * d0 + bb0, acc[m][n][1] * d0 + bb0);
            float2 v1 = make_float2(acc[m][n][2] * d1 + bb1, acc[m][n][3] * d1 + bb1);
            *(float2*)(r0 + px) = v0;
            *(float2*)(r1 + px) = v1;
        }
    }
}

// ---------------------------------------------------------------------------
extern "C" void kernel_launch(void* const* d_in, const int* in_sizes, int n_in,
                              void* d_out, int out_size) {
    const float* x       = (const float*)d_in[0];
    const float* w       = (const float*)d_in[1];
    const float* weight  = (const float*)d_in[2];
    const float* style_W = (const float*)d_in[3];
    const float* style_b = (const float*)d_in[4];
    const float* bias    = (const float*)d_in[5];
    float* out = (float*)d_out;

    prep_style<<<Bq, 128>>>(w, style_W, style_b);
    prep_w2<<<64, 256>>>(weight);
    prepack_kernel<<<576, 256>>>(weight);
    prep_demod<<<128, 256>>>();

    dim3 grid(2, HH, Bq);
    conv_mma_kernel<<<grid, 256>>>(x, bias, out);
}

// round 6
// speedup vs baseline: 3.3591x; 1.1284x over previous
#include <cuda_runtime.h>
#include <cuda_fp16.h>
#include <cstdint>

#define Bq    8
#define CIN   128
#define COUT  128
#define HH    256
#define WW    256
#define SDIM  512

#define STW   132          // stage stride (floats): c-row offsets {0,8,16,24} mod 32 -> conflict-free

__device__ float  g_style[Bq * CIN];
__device__ float  g_demod[Bq * COUT];
__device__ float  g_W2[COUT * CIN];
__device__ __half g_wA[36 * 8192];   // 36 steps x (2kk x 8mt x 32lane x 8 halves), fragment-ordered

#define MMA_F16(d, a, bb)                                                 \
    asm volatile("mma.sync.aligned.m16n8k16.row.col.f32.f16.f16.f32 "     \
                 "{%0,%1,%2,%3}, {%4,%5,%6,%7}, {%8,%9}, {%0,%1,%2,%3};"  \
                 : "+f"((d)[0]), "+f"((d)[1]), "+f"((d)[2]), "+f"((d)[3]) \
                 : "r"((a)[0]), "r"((a)[1]), "r"((a)[2]), "r"((a)[3]),    \
                   "r"((bb)[0]), "r"((bb)[1]))

// ---------------------------------------------------------------------------
// prologue kernels (proven in R5, ~10 us total)
// ---------------------------------------------------------------------------
__global__ void prep_style(const float* __restrict__ w,
                           const float* __restrict__ style_W,
                           const float* __restrict__ style_b) {
    const int b = blockIdx.x, o = threadIdx.x;
    const float4* wv = (const float4*)(w + (size_t)b * SDIM);
    const float4* Wv = (const float4*)(style_W + (size_t)o * SDIM);
    float acc = 0.f;
    #pragma unroll 8
    for (int k = 0; k < SDIM / 4; k++) {
        float4 a = wv[k], c = Wv[k];
        acc += a.x * c.x + a.y * c.y + a.z * c.z + a.w * c.w;
    }
    g_style[b * CIN + o] = acc + style_b[o];
}

__global__ void prep_w2(const float* __restrict__ weight) {
    int idx = blockIdx.x * 256 + threadIdx.x;
    const float* p = weight + (size_t)idx * 9;
    float s = 0.f;
    #pragma unroll
    for (int t = 0; t < 9; t++) { float v = p[t]; s += v * v; }
    g_W2[idx] = s;
}

__global__ void prep_demod(void) {
    int gw   = blockIdx.x * 8 + (threadIdx.x >> 5);
    int lane = threadIdx.x & 31;
    int b = gw >> 7, o = gw & 127;
    float sum = 0.f;
    #pragma unroll
    for (int j = 0; j < 4; j++) {
        int i = lane + j * 32;
        float s = g_style[b * CIN + i];
        sum += s * s * g_W2[o * CIN + i];
    }
    #pragma unroll
    for (int d = 16; d > 0; d >>= 1)
        sum += __shfl_xor_sync(0xffffffffu, sum, d);
    if (lane == 0) g_demod[b * COUT + o] = rsqrtf(sum + 1e-8f);
}

// prepack weights into m16n8k16 fp16 A-fragment order:
// half index = ((s*2+kk)*8+mt)*256 + lane*8 + j*2 + h
//   m  = mt*16 + (lane>>2) + 8*(j&1)
//   kl = kk*16 + (lane&3)*2 + 8*(j>>1) + h
__global__ void prepack_kernel(const float* __restrict__ weight) {
    int idx = blockIdx.x * 256 + threadIdx.x;      // < 294912
    int h    = idx & 1;
    int j    = (idx >> 1) & 3;
    int lane = (idx >> 3) & 31;
    int mt   = (idx >> 8) & 7;
    int kk   = (idx >> 11) & 1;
    int s    = idx >> 12;                          // 0..35
    int dx = s % 3;
    int g  = s / 3;
    int dy = g >> 2, chunk = g & 3;
    int m  = mt * 16 + (lane >> 2) + 8 * (j & 1);
    int kl = kk * 16 + (lane & 3) * 2 + 8 * (j >> 1) + h;
    int c  = chunk * 32 + kl;
    g_wA[idx] = __float2half_rn(weight[((size_t)m * CIN + c) * 9 + dy * 3 + dx]);
}

// ---------------------------------------------------------------------------
// main conv: CTA = (xhalf, y, b). M=128 x N=128 x K=1152, fp16 m16n8k16.
// 8 warps = 2(wm: 64oc) x 4(wn: 32px); warp tile 64x32; acc 4x4x4 = 64 regs.
// ---------------------------------------------------------------------------
__global__ __launch_bounds__(256, 2)
void conv_mma_kernel(const float* __restrict__ x,
                     const float* __restrict__ bias,
                     float* __restrict__ out) {
    __shared__ float styl[CIN];
    __shared__ float stage[2][32 * STW];

    const int tid  = threadIdx.x;
    const int lane = tid & 31;
    const int warp = tid >> 5;
    const int wm   = warp >> 2;      // 0..1
    const int wn   = warp & 3;       // 0..3
    const int xh   = blockIdx.x;
    const int y    = blockIdx.y;
    const int b    = blockIdx.z;
    const int x0   = xh * 128;

    const int gid = lane >> 2;       // 0..7
    const int tig = lane & 3;        // 0..3

    if (tid < CIN) styl[tid] = g_style[b * CIN + tid];
    __syncthreads();

    float acc[4][4][4];
    #pragma unroll
    for (int m = 0; m < 4; m++)
        #pragma unroll
        for (int n = 0; n < 4; n++)
            #pragma unroll
            for (int j = 0; j < 4; j++) acc[m][n][j] = 0.f;

    // ---- fill one stage buffer for group g (32 ch x 130 halo px, fp32) ----
    auto fill = [&](int g, float* buf) {
        const int dy = g >> 2, chunk = g & 3;
        const int yr = y + dy - 1;
        const bool yok = (yr >= 0) && (yr < HH);
        const int c0 = chunk * 32;
        const float* xrow = x + (((size_t)b * CIN + c0) * HH + yr) * WW;
        #pragma unroll 1
        for (int it = tid; it < 32 * 130; it += 256) {
            int c = it / 130;
            int q = it - c * 130;
            int gx = x0 - 1 + q;
            float v = 0.f;
            if (yok && (unsigned)gx < (unsigned)WW)
                v = __ldg(xrow + (size_t)c * HH * WW + gx) * styl[c0 + c];
            buf[c * STW + q] = v;
        }
    };

    // ---- one K-step: 32 MMAs/warp, A from prepacked gmem, B from stage ----
    auto compute = [&](const float* stg, int dx, int s) {
        #pragma unroll
        for (int kk = 0; kk < 2; kk++) {
            const uint4* As = ((const uint4*)g_wA) +
                              (((size_t)(s * 2 + kk) * 8 + wm * 4) * 32 + lane);
            uint4 af[4];
            #pragma unroll
            for (int m = 0; m < 4; m++) af[m] = __ldg(As + m * 32);

            uint32_t bb[4][2];
            #pragma unroll
            for (int n = 0; n < 4; n++) {
                const float* col = stg + (kk * 16 + tig * 2) * STW +
                                   (wn * 4 + n) * 8 + gid + dx;
                float lo0 = col[0],       lo1 = col[STW];
                float hi0 = col[8 * STW], hi1 = col[9 * STW];
                __half2 l = __float22half2_rn(make_float2(lo0, lo1));
                __half2 h = __float22half2_rn(make_float2(hi0, hi1));
                bb[n][0] = *(uint32_t*)&l;
                bb[n][1] = *(uint32_t*)&h;
            }
            #pragma unroll
            for (int m = 0; m < 4; m++) {
                const uint32_t* a = (const uint32_t*)&af[m];
                #pragma unroll
                for (int n = 0; n < 4; n++)
                    MMA_F16(acc[m][n], a, bb[n]);
            }
        }
    };

    fill(0, stage[0]);
    __syncthreads();

    #pragma unroll 1
    for (int g = 0; g < 12; g++) {
        const int cur = g & 1;
        const int s0  = g * 3;
        compute(stage[cur], 0, s0);
        if (g < 11) fill(g + 1, stage[cur ^ 1]);   // overlaps dx=1,2 compute
        compute(stage[cur], 1, s0 + 1);
        compute(stage[cur], 2, s0 + 2);
        __syncthreads();
    }

    // ---- epilogue: demod + bias, float2 stores ----
    #pragma unroll
    for (int m = 0; m < 4; m++) {
        const int oc0 = (wm * 4 + m) * 16 + gid;
        const int oc1 = oc0 + 8;
        const float d0 = g_demod[b * COUT + oc0], bb0 = bias[oc0];
        const float d1 = g_demod[b * COUT + oc1], bb1 = bias[oc1];
        float* r0 = out + (((size_t)b * COUT + oc0) * HH + y) * WW;
        float* r1 = out + (((size_t)b * COUT + oc1) * HH + y) * WW;
        #pragma unroll
        for (int n = 0; n < 4; n++) {
            const int px = x0 + (wn * 4 + n) * 8 + tig * 2;
            float2 v0 = make_float2(acc[m][n][0] * d0 + bb0, acc[m][n][1] * d0 + bb0);
            float2 v1 = make_float2(acc[m][n][2] * d1 + bb1, acc[m][n][3] * d1 + bb1);
            *(float2*)(r0 + px) = v0;
            *(float2*)(r1 + px) = v1;
        }
    }
}

// ---------------------------------------------------------------------------
extern "C" void kernel_launch(void* const* d_in, const int* in_sizes, int n_in,
                              void* d_out, int out_size) {
    const float* x       = (const float*)d_in[0];
    const float* w       = (const float*)d_in[1];
    const float* weight  = (const float*)d_in[2];
    const float* style_W = (const float*)d_in[3];
    const float* style_b = (const float*)d_in[4];
    const float* bias    = (const float*)d_in[5];
    float* out = (float*)d_out;

    prep_style<<<Bq, 128>>>(w, style_W, style_b);
    prep_w2<<<64, 256>>>(weight);
    prepack_kernel<<<1152, 256>>>(weight);
    prep_demod<<<128, 256>>>();

    dim3 grid(2, HH, Bq);
    conv_mma_kernel<<<grid, 256>>>(x, bias, out);
}

// round 7
// speedup vs baseline: 7.5984x; 2.2620x over previous
#include <cuda_runtime.h>
#include <cuda_fp16.h>
#include <cstdint>

#define Bq    8
#define CIN   128
#define COUT  128
#define HH    256
#define WW    256
#define SDIM  512

#define PXW   20     // words (half2) per px row in stage: 16 used + 4 pad; 20=4*5 -> conflict-free

__device__ float  g_style[Bq * CIN];
__device__ float  g_demod[Bq * COUT];
__device__ float  g_W2[COUT * CIN];
__device__ __half g_wA[36 * 8192];   // fragment-ordered fp16 weights (proven R6 mapping)

#define MMA_F16(d, a, bb)                                                 \
    asm volatile("mma.sync.aligned.m16n8k16.row.col.f32.f16.f16.f32 "     \
                 "{%0,%1,%2,%3}, {%4,%5,%6,%7}, {%8,%9}, {%0,%1,%2,%3};"  \
                 : "+f"((d)[0]), "+f"((d)[1]), "+f"((d)[2]), "+f"((d)[3]) \
                 : "r"((a)[0]), "r"((a)[1]), "r"((a)[2]), "r"((a)[3]),    \
                   "r"((bb)[0]), "r"((bb)[1]))

// ---------------------------------------------------------------------------
// prep1: style GEMV (blocks 0..7) + per-(o,i) weight tap-energy (blocks 8..71)
// ---------------------------------------------------------------------------
__global__ void prep1(const float* __restrict__ w,
                      const float* __restrict__ style_W,
                      const float* __restrict__ style_b,
                      const float* __restrict__ weight) {
    if (blockIdx.x < 8) {
        if (threadIdx.x < 128) {
            const int b = blockIdx.x, o = threadIdx.x;
            const float4* wv = (const float4*)(w + (size_t)b * SDIM);
            const float4* Wv = (const float4*)(style_W + (size_t)o * SDIM);
            float acc = 0.f;
            #pragma unroll 8
            for (int k = 0; k < SDIM / 4; k++) {
                float4 a = wv[k], c = Wv[k];
                acc += a.x * c.x + a.y * c.y + a.z * c.z + a.w * c.w;
            }
            g_style[b * CIN + o] = acc + style_b[o];
        }
    } else {
        int idx = (blockIdx.x - 8) * 256 + threadIdx.x;   // < 16384
        const float* p = weight + (size_t)idx * 9;
        float s = 0.f;
        #pragma unroll
        for (int t = 0; t < 9; t++) { float v = p[t]; s += v * v; }
        g_W2[idx] = s;
    }
}

// ---------------------------------------------------------------------------
// prep2: prepack (blocks 0..1151) + demod (blocks 1152..1279)
// fragment mapping identical to R6 (passed, rel_err 2.9e-4)
// ---------------------------------------------------------------------------
__global__ void prep2(const float* __restrict__ weight) {
    if (blockIdx.x < 1152) {
        int idx = blockIdx.x * 256 + threadIdx.x;      // < 294912
        int h    = idx & 1;
        int j    = (idx >> 1) & 3;
        int lane = (idx >> 3) & 31;
        int mt   = (idx >> 8) & 7;
        int kk   = (idx >> 11) & 1;
        int s    = idx >> 12;                          // 0..35
        int dx = s % 3;
        int g  = s / 3;
        int dy = g >> 2, chunk = g & 3;
        int m  = mt * 16 + (lane >> 2) + 8 * (j & 1);
        int kl = kk * 16 + (lane & 3) * 2 + 8 * (j >> 1) + h;
        int c  = chunk * 32 + kl;
        g_wA[idx] = __float2half_rn(weight[((size_t)m * CIN + c) * 9 + dy * 3 + dx]);
    } else {
        int gw   = (blockIdx.x - 1152) * 8 + (threadIdx.x >> 5);  // 0..1023
        int lane = threadIdx.x & 31;
        int b = gw >> 7, o = gw & 127;
        float sum = 0.f;
        #pragma unroll
        for (int j = 0; j < 4; j++) {
            int i = lane + j * 32;
            float s = g_style[b * CIN + i];
            sum += s * s * g_W2[o * CIN + i];
        }
        #pragma unroll
        for (int d = 16; d > 0; d >>= 1)
            sum += __shfl_xor_sync(0xffffffffu, sum, d);
        if (lane == 0) g_demod[b * COUT + o] = rsqrtf(sum + 1e-8f);
    }
}

// ---------------------------------------------------------------------------
// main conv: CTA = (xhalf, y, b). M=128 x N=128 x K=1152, fp16 m16n8k16.
// Stage is fp16 half2, TRANSPOSED [px][cpair] -> B fragment = 1 LDS.b32/reg.
// ---------------------------------------------------------------------------
__global__ __launch_bounds__(256, 2)
void conv_mma_kernel(const float* __restrict__ x,
                     const float* __restrict__ bias,
                     float* __restrict__ out) {
    __shared__ float    styl[CIN];
    __shared__ uint32_t stage[2][130 * PXW];

    const int tid  = threadIdx.x;
    const int lane = tid & 31;
    const int warp = tid >> 5;
    const int wm   = warp >> 2;      // 0..1
    const int wn   = warp & 3;       // 0..3
    const int xh   = blockIdx.x;
    const int y    = blockIdx.y;
    const int b    = blockIdx.z;
    const int x0   = xh * 128;

    const int gid = lane >> 2;       // 0..7
    const int tig = lane & 3;        // 0..3

    if (tid < CIN) styl[tid] = g_style[b * CIN + tid];
    __syncthreads();

    float acc[4][4][4];
    #pragma unroll
    for (int m = 0; m < 4; m++)
        #pragma unroll
        for (int n = 0; n < 4; n++)
            #pragma unroll
            for (int j = 0; j < 4; j++) acc[m][n][j] = 0.f;

    // ---- fill: 32 ch x 130 halo px -> half2 transposed stage ----
    // warp covers 8 px x 4 cp per instr (lane: px=gid, cp=tig) -> conflict-free STS
    auto fill = [&](int g, uint32_t* buf) {
        const int dy = g >> 2, chunk = g & 3;
        const int yr = y + dy - 1;
        const bool yok = (unsigned)yr < (unsigned)HH;
        const int c0 = chunk * 32;
        const float* xp = x + (((size_t)b * CIN + c0) * HH + yr) * WW;
        #pragma unroll
        for (int jj = 0; jj < 2; jj++) {
            const int px = warp * 8 + gid + jj * 64;
            const int gx = x0 - 1 + px;
            const bool ok = yok && ((unsigned)gx < (unsigned)WW);
            #pragma unroll
            for (int ii = 0; ii < 4; ii++) {
                const int cp = tig + ii * 4;
                float v0 = 0.f, v1 = 0.f;
                if (ok) {
                    v0 = __ldg(xp + (size_t)(2 * cp)     * HH * WW + gx) * styl[c0 + 2 * cp];
                    v1 = __ldg(xp + (size_t)(2 * cp + 1) * HH * WW + gx) * styl[c0 + 2 * cp + 1];
                }
                __half2 hv = __floats2half2_rn(v0, v1);
                buf[px * PXW + cp] = *(uint32_t*)&hv;
            }
        }
        // tail px 128,129 by warp 0
        if (warp == 0) {
            const int px = 128 + (lane >> 4);
            const int cp = lane & 15;
            const int gx = x0 - 1 + px;
            const bool ok = yok && ((unsigned)gx < (unsigned)WW);
            float v0 = 0.f, v1 = 0.f;
            if (ok) {
                v0 = __ldg(xp + (size_t)(2 * cp)     * HH * WW + gx) * styl[c0 + 2 * cp];
                v1 = __ldg(xp + (size_t)(2 * cp + 1) * HH * WW + gx) * styl[c0 + 2 * cp + 1];
            }
            __half2 hv = __floats2half2_rn(v0, v1);
            buf[px * PXW + cp] = *(uint32_t*)&hv;
        }
    };

    // ---- one K-step: 32 MMAs/warp; A LDG.128 (L1-hot), B 1 LDS.b32/reg ----
    auto compute = [&](const uint32_t* stg, int dx, int s) {
        #pragma unroll
        for (int kk = 0; kk < 2; kk++) {
            const uint4* As = ((const uint4*)g_wA) +
                              (((size_t)(s * 2 + kk) * 8 + wm * 4) * 32 + lane);
            uint4 af[4];
            #pragma unroll
            for (int m = 0; m < 4; m++) af[m] = __ldg(As + m * 32);

            uint32_t bb[4][2];
            #pragma unroll
            for (int n = 0; n < 4; n++) {
                const int px = wn * 32 + n * 8 + gid + dx;
                const uint32_t* p = stg + px * PXW + kk * 8 + tig;
                bb[n][0] = p[0];
                bb[n][1] = p[4];
            }
            #pragma unroll
            for (int m = 0; m < 4; m++) {
                const uint32_t* a = (const uint32_t*)&af[m];
                #pragma unroll
                for (int n = 0; n < 4; n++)
                    MMA_F16(acc[m][n], a, bb[n]);
            }
        }
    };

    fill(0, stage[0]);
    __syncthreads();

    #pragma unroll 1
    for (int g = 0; g < 12; g++) {
        const int cur = g & 1;
        const int s0  = g * 3;
        compute(stage[cur], 0, s0);
        if (g < 11) fill(g + 1, stage[cur ^ 1]);   // overlaps dx=1,2 compute
        compute(stage[cur], 1, s0 + 1);
        compute(stage[cur], 2, s0 + 2);
        __syncthreads();
    }

    // ---- epilogue: demod + bias, float2 stores ----
    #pragma unroll
    for (int m = 0; m < 4; m++) {
        const int oc0 = (wm * 4 + m) * 16 + gid;
        const int oc1 = oc0 + 8;
        const float d0 = g_demod[b * COUT + oc0], bb0 = bias[oc0];
        const float d1 = g_demod[b * COUT + oc1], bb1 = bias[oc1];
        float* r0 = out + (((size_t)b * COUT + oc0) * HH + y) * WW;
        float* r1 = out + (((size_t)b * COUT + oc1) * HH + y) * WW;
        #pragma unroll
        for (int n = 0; n < 4; n++) {
            const int px = x0 + (wn * 4 + n) * 8 + tig * 2;
            float2 v0 = make_float2(acc[m][n][0] * d0 + bb0, acc[m][n][1] * d0 + bb0);
            float2 v1 = make_float2(acc[m][n][2] * d1 + bb1, acc[m][n][3] * d1 + bb1);
            *(float2*)(r0 + px) = v0;
            *(float2*)(r1 + px) = v1;
        }
    }
}

// ---------------------------------------------------------------------------
extern "C" void kernel_launch(void* const* d_in, const int* in_sizes, int n_in,
                              void* d_out, int out_size) {
    const float* x       = (const float*)d_in[0];
    const float* w       = (const float*)d_in[1];
    const float* weight  = (const float*)d_in[2];
    const float* style_W = (const float*)d_in[3];
    const float* style_b = (const float*)d_in[4];
    const float* bias    = (const float*)d_in[5];
    float* out = (float*)d_out;

    prep1<<<72, 256>>>(w, style_W, style_b, weight);
    prep2<<<1280, 256>>>(weight);

    dim3 grid(2, HH, Bq);
    conv_mma_kernel<<<grid, 256>>>(x, bias, out);
}